// round 3
// baseline (speedup 1.0000x reference)
#include <cuda_runtime.h>
#include <math.h>

#define H   1024
#define H2  2048
#define H3  3072
#define SS  4096
#define V   50257
#define VPAD 50264          // 6283 blocks * 8 rows, divisible by 4

// ---- scratch (no allocations allowed) ----
__device__ float g_gi[H3];
__device__ float g_gh[H3];
__device__ float g_scores[SS];
__device__ float g_attn[SS];
__device__ float g_y[H2];            // [h_new, context]
__device__ float4 g_cpart[128][H / 4]; // context partials (deterministic)
__device__ float g_logits[VPAD + 8];
__device__ float g_red[2];           // max, log(sumexp)
__device__ unsigned int g_ctr;       // logits completion counter (self-resetting)

// output layout (tuple order): output[V], context[H], h_new[H], attn[S]
#define OUT_OUTPUT  0
#define OUT_CONTEXT (V)
#define OUT_HNEW    (V + H)
#define OUT_ATTN    (V + 2 * H)

__device__ __forceinline__ float warpReduceSum(float v) {
    #pragma unroll
    for (int o = 16; o > 0; o >>= 1) v += __shfl_down_sync(0xffffffffu, v, o);
    return v;
}
__device__ __forceinline__ float warpReduceMax(float v) {
    #pragma unroll
    for (int o = 16; o > 0; o >>= 1) v = fmaxf(v, __shfl_down_sync(0xffffffffu, v, o));
    return v;
}
__device__ __forceinline__ float dot4(float4 a, float4 b) {
    return a.x * b.x + a.y * b.y + a.z * b.z + a.w * b.w;
}

// K1: gi = w_ih@[emb,ctx] + b_ih ; gh = w_hh@h + b_hh.
// Warp-per-row, 8 rows/block. Blocks [0,384): w_ih. Blocks [384,768): w_hh.
__global__ void __launch_bounds__(256) k_gates(
        const int* __restrict__ word,
        const float* __restrict__ emb,
        const float* __restrict__ ctx,
        const float* __restrict__ w_ih,
        const float* __restrict__ w_hh,
        const float* __restrict__ b_ih,
        const float* __restrict__ b_hh,
        const float* __restrict__ h) {
    __shared__ float4 sv[H2 / 4];
    int b = blockIdx.x;
    int tid = threadIdx.x;
    bool ih = (b < 384);
    if (ih) {
        const float4* e4 = (const float4*)(emb + (size_t)word[0] * H);
        sv[tid] = e4[tid];
        sv[256 + tid] = ((const float4*)ctx)[tid];
    } else {
        sv[tid] = ((const float4*)h)[tid];
    }
    __syncthreads();

    int warp = tid >> 5, lane = tid & 31;
    if (ih) {
        int row = b * 8 + warp;
        const float4* w4 = (const float4*)(w_ih + (size_t)row * H2);
        float acc = 0.f;
        #pragma unroll
        for (int i = 0; i < 16; i++) {
            int j = lane + 32 * i;
            acc += dot4(__ldcs(w4 + j), sv[j]);
        }
        acc = warpReduceSum(acc);
        if (lane == 0) g_gi[row] = acc + b_ih[row];
    } else {
        int row = (b - 384) * 8 + warp;
        const float4* w4 = (const float4*)(w_hh + (size_t)row * H);
        float acc = 0.f;
        #pragma unroll
        for (int i = 0; i < 8; i++) {
            int j = lane + 32 * i;
            acc += dot4(__ldcs(w4 + j), sv[j]);
        }
        acc = warpReduceSum(acc);
        if (lane == 0) g_gh[row] = acc + b_hh[row];
    }
}

// K2: fused GRU pointwise (recomputed per block into smem) + attention scores.
// Warp-per-row, 8 rows/block, 512 blocks. Block 0 also publishes h_new.
__global__ void __launch_bounds__(256) k_scores(
        const float* __restrict__ enc,
        const float* __restrict__ h,
        float* __restrict__ out) {
    __shared__ float4 sh[H / 4];
    int tid = threadIdx.x;
    for (int i = tid; i < H; i += 256) {
        float r = 1.f / (1.f + expf(-(g_gi[i]     + g_gh[i])));
        float z = 1.f / (1.f + expf(-(g_gi[H + i] + g_gh[H + i])));
        float n = tanhf(g_gi[2 * H + i] + r * g_gh[2 * H + i]);
        float hn = (1.f - z) * n + z * h[i];
        ((float*)sh)[i] = hn;
        if (blockIdx.x == 0) {
            g_y[i] = hn;
            out[OUT_HNEW + i] = hn;
        }
    }
    __syncthreads();

    int warp = tid >> 5, lane = tid & 31;
    int row = blockIdx.x * 8 + warp;
    const float4* e4 = (const float4*)(enc + (size_t)row * H);
    float acc = 0.f;
    #pragma unroll
    for (int i = 0; i < 8; i++) {
        int j = lane + 32 * i;
        acc += dot4(e4[j], sh[j]);
    }
    acc = warpReduceSum(acc);
    if (lane == 0) g_scores[row] = acc;
}

// K3: softmax over S=4096 (single block). Writes attn output slot.
__global__ void k_softmax(float* __restrict__ out) {
    __shared__ float sred[32];
    __shared__ float sM, sSum;
    int tid = threadIdx.x;
    int wid = tid >> 5, lane = tid & 31;

    float m = -1e30f;
    for (int i = tid; i < SS; i += 1024) m = fmaxf(m, g_scores[i]);
    m = warpReduceMax(m);
    if (lane == 0) sred[wid] = m;
    __syncthreads();
    if (wid == 0) {
        m = sred[lane];
        m = warpReduceMax(m);
        if (lane == 0) sM = m;
    }
    __syncthreads();
    float M = sM;

    float s = 0.f;
    for (int i = tid; i < SS; i += 1024) s += expf(g_scores[i] - M);
    s = warpReduceSum(s);
    if (lane == 0) sred[wid] = s;
    __syncthreads();
    if (wid == 0) {
        s = sred[lane];
        s = warpReduceSum(s);
        if (lane == 0) sSum = s;
    }
    __syncthreads();
    float inv = 1.f / sSum;

    for (int i = tid; i < SS; i += 1024) {
        float a = expf(g_scores[i] - M) * inv;
        g_attn[i] = a;
        out[OUT_ATTN + i] = a;
    }
}

// K4a: context partials. 128 blocks (s-chunks of 32 rows), 256 threads.
// Each thread owns one float4 column (256*4 = 1024 cols). Fully unrolled ->
// 32 independent 16B loads in flight per thread.
__global__ void __launch_bounds__(256) k_ctx_part(const float* __restrict__ enc) {
    int c4 = threadIdx.x;              // float4 column index 0..255
    int s0 = blockIdx.x * 32;
    const float4* e4 = (const float4*)enc;
    float4 acc = make_float4(0.f, 0.f, 0.f, 0.f);
    #pragma unroll
    for (int k = 0; k < 32; k++) {
        float a = g_attn[s0 + k];
        float4 e = e4[(size_t)(s0 + k) * (H / 4) + c4];
        acc.x += a * e.x; acc.y += a * e.y; acc.z += a * e.z; acc.w += a * e.w;
    }
    g_cpart[blockIdx.x][c4] = acc;
}

// K4b: sum 128 partials per column (deterministic). Writes context + y[H:2H].
__global__ void k_ctx_sum(float* __restrict__ out) {
    int col = threadIdx.x;             // 1024 threads, one scalar column each
    const float* cp = (const float*)g_cpart;
    float acc = 0.f;
    #pragma unroll 16
    for (int p = 0; p < 128; p++) acc += cp[p * H + col];
    out[OUT_CONTEXT + col] = acc;
    g_y[H + col] = acc;
}

// K5: logits = out_w @ y + out_b, warp per row, 8 rows/block, streaming loads.
// Tail: last block (atomic counter) computes log-softmax stats into g_red.
// Rows >= V get -INF so the padded float4 reduction over VPAD is exact.
__global__ void __launch_bounds__(256) k_logits(const float* __restrict__ out_w,
                                                const float* __restrict__ out_b) {
    __shared__ float4 sy[H2 / 4];
    for (int j = threadIdx.x; j < H2 / 4; j += blockDim.x)
        sy[j] = ((const float4*)g_y)[j];
    __syncthreads();

    int warp = threadIdx.x >> 5, lane = threadIdx.x & 31;
    int row = blockIdx.x * 8 + warp;

    if (row < V) {
        const float4* w4 = (const float4*)(out_w + (size_t)row * H2);
        float acc = 0.f;
        #pragma unroll
        for (int i = 0; i < 16; i++) {
            int j = lane + 32 * i;
            acc += dot4(__ldcs(w4 + j), sy[j]);
        }
        acc = warpReduceSum(acc);
        if (lane == 0) g_logits[row] = acc + out_b[row];
    } else if (lane == 0) {
        g_logits[row] = -INFINITY;     // pad rows [V, VPAD)
    }

    // ---- last-block log-softmax reduction ----
    __shared__ bool isLast;
    __shared__ float sred[8];
    __shared__ float sM;
    __threadfence();
    __syncthreads();
    if (threadIdx.x == 0) {
        unsigned int old = atomicAdd(&g_ctr, 1u);
        isLast = (old == gridDim.x - 1);
    }
    __syncthreads();
    if (!isLast) return;

    const float4* l4 = (const float4*)g_logits;
    float m = -INFINITY;
    for (int i = threadIdx.x; i < VPAD / 4; i += 256) {
        float4 v = l4[i];
        m = fmaxf(m, fmaxf(fmaxf(v.x, v.y), fmaxf(v.z, v.w)));
    }
    m = warpReduceMax(m);
    if (lane == 0) sred[warp] = m;
    __syncthreads();
    if (warp == 0) {
        m = (lane < 8) ? sred[lane] : -INFINITY;
        m = warpReduceMax(m);
        if (lane == 0) sM = m;
    }
    __syncthreads();
    float M = sM;

    float s = 0.f;
    for (int i = threadIdx.x; i < VPAD / 4; i += 256) {
        float4 v = l4[i];
        s += expf(v.x - M) + expf(v.y - M) + expf(v.z - M) + expf(v.w - M);
    }
    s = warpReduceSum(s);
    if (lane == 0) sred[warp] = s;
    __syncthreads();
    if (warp == 0) {
        s = (lane < 8) ? sred[lane] : 0.f;
        s = warpReduceSum(s);
        if (lane == 0) {
            g_red[0] = M;
            g_red[1] = logf(s);
            g_ctr = 0;                 // reset for next graph replay
        }
    }
}

// K6: output = logits - max - log(sumexp)
__global__ void k_lsm_write(float* __restrict__ out) {
    int i = blockIdx.x * blockDim.x + threadIdx.x;
    if (i < V) out[OUT_OUTPUT + i] = g_logits[i] - g_red[0] - g_red[1];
}

extern "C" void kernel_launch(void* const* d_in, const int* in_sizes, int n_in,
                              void* d_out, int out_size) {
    const int*   word         = (const int*)d_in[0];
    const float* last_context = (const float*)d_in[1];
    const float* last_hidden  = (const float*)d_in[2];
    const float* enc          = (const float*)d_in[3];
    const float* embedding    = (const float*)d_in[4];
    const float* w_ih         = (const float*)d_in[5];
    const float* w_hh         = (const float*)d_in[6];
    const float* b_ih         = (const float*)d_in[7];
    const float* b_hh         = (const float*)d_in[8];
    const float* out_w        = (const float*)d_in[9];
    const float* out_b        = (const float*)d_in[10];
    float* out = (float*)d_out;

    k_gates    <<<768, 256>>>(word, embedding, last_context, w_ih, w_hh,
                              b_ih, b_hh, last_hidden);
    k_scores   <<<512, 256>>>(enc, last_hidden, out);
    k_softmax  <<<1, 1024>>>(out);
    k_ctx_part <<<128, 256>>>(enc);
    k_ctx_sum  <<<1, 1024>>>(out);
    k_logits   <<<(V + 7) / 8, 256>>>(out_w, out_b);
    k_lsm_write<<<(V + 255) / 256, 256>>>(out);
}

// round 4
// speedup vs baseline: 1.0466x; 1.0466x over previous
#include <cuda_runtime.h>
#include <math.h>

#define H   1024
#define H2  2048
#define H3  3072
#define SS  4096
#define V   50257

#define NPART 512            // ctx partial chunks (8 rows each)

// ---- scratch (no allocations allowed) ----
__device__ float g_gi[H3];
__device__ float g_gh[H3];
__device__ float g_scores[SS];
__device__ float g_attn[SS];
__device__ float g_y[H2];                  // [h_new, context]
__device__ float4 g_cpart[NPART][H / 4];   // context partials (deterministic)
__device__ float g_logits[V + 16];
__device__ float g_red[2];                 // max, log(sumexp)

// output layout (tuple order): output[V], context[H], h_new[H], attn[S]
#define OUT_OUTPUT  0
#define OUT_CONTEXT (V)
#define OUT_HNEW    (V + H)
#define OUT_ATTN    (V + 2 * H)

__device__ __forceinline__ float warpReduceSum(float v) {
    #pragma unroll
    for (int o = 16; o > 0; o >>= 1) v += __shfl_down_sync(0xffffffffu, v, o);
    return v;
}
__device__ __forceinline__ float warpReduceMax(float v) {
    #pragma unroll
    for (int o = 16; o > 0; o >>= 1) v = fmaxf(v, __shfl_down_sync(0xffffffffu, v, o));
    return v;
}
__device__ __forceinline__ float dot4(float4 a, float4 b) {
    return a.x * b.x + a.y * b.y + a.z * b.z + a.w * b.w;
}

// K1: gi = w_ih@[emb,ctx] + b_ih ; gh = w_hh@h + b_hh.
// Warp-per-row, 8 rows/block. Blocks [0,384): w_ih. Blocks [384,768): w_hh.
__global__ void __launch_bounds__(256) k_gates(
        const int* __restrict__ word,
        const float* __restrict__ emb,
        const float* __restrict__ ctx,
        const float* __restrict__ w_ih,
        const float* __restrict__ w_hh,
        const float* __restrict__ b_ih,
        const float* __restrict__ b_hh,
        const float* __restrict__ h) {
    __shared__ float4 sv[H2 / 4];
    int b = blockIdx.x;
    int tid = threadIdx.x;
    bool ih = (b < 384);
    if (ih) {
        const float4* e4 = (const float4*)(emb + (size_t)word[0] * H);
        sv[tid] = e4[tid];
        sv[256 + tid] = ((const float4*)ctx)[tid];
    } else {
        sv[tid] = ((const float4*)h)[tid];
    }
    __syncthreads();

    int warp = tid >> 5, lane = tid & 31;
    if (ih) {
        int row = b * 8 + warp;
        const float4* w4 = (const float4*)(w_ih + (size_t)row * H2);
        float acc = 0.f;
        #pragma unroll
        for (int i = 0; i < 16; i++) {
            int j = lane + 32 * i;
            acc += dot4(__ldcs(w4 + j), sv[j]);
        }
        acc = warpReduceSum(acc);
        if (lane == 0) g_gi[row] = acc + b_ih[row];
    } else {
        int row = (b - 384) * 8 + warp;
        const float4* w4 = (const float4*)(w_hh + (size_t)row * H);
        float acc = 0.f;
        #pragma unroll
        for (int i = 0; i < 8; i++) {
            int j = lane + 32 * i;
            acc += dot4(__ldcs(w4 + j), sv[j]);
        }
        acc = warpReduceSum(acc);
        if (lane == 0) g_gh[row] = acc + b_hh[row];
    }
}

// K2: fused GRU pointwise (recomputed per block into smem) + attention scores.
// Warp-per-row, 8 rows/block, 512 blocks. Block 0 also publishes h_new.
__global__ void __launch_bounds__(256) k_scores(
        const float* __restrict__ enc,
        const float* __restrict__ h,
        float* __restrict__ out) {
    __shared__ float4 sh[H / 4];
    int tid = threadIdx.x;
    for (int i = tid; i < H; i += 256) {
        float r = 1.f / (1.f + expf(-(g_gi[i]     + g_gh[i])));
        float z = 1.f / (1.f + expf(-(g_gi[H + i] + g_gh[H + i])));
        float n = tanhf(g_gi[2 * H + i] + r * g_gh[2 * H + i]);
        float hn = (1.f - z) * n + z * h[i];
        ((float*)sh)[i] = hn;
        if (blockIdx.x == 0) {
            g_y[i] = hn;
            out[OUT_HNEW + i] = hn;
        }
    }
    __syncthreads();

    int warp = tid >> 5, lane = tid & 31;
    int row = blockIdx.x * 8 + warp;
    const float4* e4 = (const float4*)(enc + (size_t)row * H);
    float acc = 0.f;
    #pragma unroll
    for (int i = 0; i < 8; i++) {
        int j = lane + 32 * i;
        acc += dot4(e4[j], sh[j]);
    }
    acc = warpReduceSum(acc);
    if (lane == 0) g_scores[row] = acc;
}

// K3: softmax over S=4096 (single block). Writes attn output slot.
__global__ void k_softmax(float* __restrict__ out) {
    __shared__ float sred[32];
    __shared__ float sM, sSum;
    int tid = threadIdx.x;
    int wid = tid >> 5, lane = tid & 31;

    float m = -1e30f;
    for (int i = tid; i < SS; i += 1024) m = fmaxf(m, g_scores[i]);
    m = warpReduceMax(m);
    if (lane == 0) sred[wid] = m;
    __syncthreads();
    if (wid == 0) {
        m = sred[lane];
        m = warpReduceMax(m);
        if (lane == 0) sM = m;
    }
    __syncthreads();
    float M = sM;

    float s = 0.f;
    for (int i = tid; i < SS; i += 1024) s += expf(g_scores[i] - M);
    s = warpReduceSum(s);
    if (lane == 0) sred[wid] = s;
    __syncthreads();
    if (wid == 0) {
        s = sred[lane];
        s = warpReduceSum(s);
        if (lane == 0) sSum = s;
    }
    __syncthreads();
    float inv = 1.f / sSum;

    for (int i = tid; i < SS; i += 1024) {
        float a = expf(g_scores[i] - M) * inv;
        g_attn[i] = a;
        out[OUT_ATTN + i] = a;
    }
}

// K4a: context partials. 512 blocks (s-chunks of 8 rows), 256 threads.
// Each thread owns one float4 column; 8 independent 16B loads in flight,
// 128K threads resident chip-wide (fixes the occupancy starvation seen in ncu).
__global__ void __launch_bounds__(256) k_ctx_part(const float* __restrict__ enc) {
    int c4 = threadIdx.x;              // float4 column index 0..255
    int s0 = blockIdx.x * 8;
    const float4* e4 = (const float4*)enc;
    float4 acc = make_float4(0.f, 0.f, 0.f, 0.f);
    #pragma unroll
    for (int k = 0; k < 8; k++) {
        float a = g_attn[s0 + k];
        float4 e = e4[(size_t)(s0 + k) * (H / 4) + c4];
        acc.x += a * e.x; acc.y += a * e.y; acc.z += a * e.z; acc.w += a * e.w;
    }
    g_cpart[blockIdx.x][c4] = acc;
}

// K4b: sum NPART partials per column (deterministic). 4 blocks x 256 threads,
// one scalar column per thread, coalesced across the partial dimension.
__global__ void __launch_bounds__(256) k_ctx_sum(float* __restrict__ out) {
    int col = blockIdx.x * 256 + threadIdx.x;
    const float* cp = (const float*)g_cpart;
    float a0 = 0.f, a1 = 0.f, a2 = 0.f, a3 = 0.f;
    #pragma unroll 8
    for (int p = 0; p < NPART; p += 4) {
        a0 += cp[(p    ) * H + col];
        a1 += cp[(p + 1) * H + col];
        a2 += cp[(p + 2) * H + col];
        a3 += cp[(p + 3) * H + col];
    }
    float acc = (a0 + a1) + (a2 + a3);
    out[OUT_CONTEXT + col] = acc;
    g_y[H + col] = acc;
}

// K5: logits = out_w @ y + out_b. Warp per row, 8 rows/block, streaming loads.
__global__ void __launch_bounds__(256) k_logits(const float* __restrict__ out_w,
                                                const float* __restrict__ out_b) {
    __shared__ float4 sy[H2 / 4];
    for (int j = threadIdx.x; j < H2 / 4; j += blockDim.x)
        sy[j] = ((const float4*)g_y)[j];
    __syncthreads();

    int warp = threadIdx.x >> 5, lane = threadIdx.x & 31;
    int row = blockIdx.x * 8 + warp;
    if (row >= V) return;  // whole warp exits together

    const float4* w4 = (const float4*)(out_w + (size_t)row * H2);
    float acc = 0.f;
    #pragma unroll
    for (int i = 0; i < 16; i++) {
        int j = lane + 32 * i;
        acc += dot4(__ldcs(w4 + j), sy[j]);
    }
    acc = warpReduceSum(acc);
    if (lane == 0) g_logits[row] = acc + out_b[row];
}

// K6: log-softmax reduction (single block, 1024 threads).
__global__ void k_lsm_red() {
    __shared__ float sred[32];
    __shared__ float sM, sSum;
    int tid = threadIdx.x;
    int wid = tid >> 5, lane = tid & 31;

    float m = -1e30f;
    for (int i = tid; i < V; i += 1024) m = fmaxf(m, g_logits[i]);
    m = warpReduceMax(m);
    if (lane == 0) sred[wid] = m;
    __syncthreads();
    if (wid == 0) {
        m = sred[lane];
        m = warpReduceMax(m);
        if (lane == 0) sM = m;
    }
    __syncthreads();
    float M = sM;

    float s = 0.f;
    for (int i = tid; i < V; i += 1024) s += expf(g_logits[i] - M);
    s = warpReduceSum(s);
    if (lane == 0) sred[wid] = s;
    __syncthreads();
    if (wid == 0) {
        s = sred[lane];
        s = warpReduceSum(s);
        if (lane == 0) sSum = s;
    }
    __syncthreads();
    if (tid == 0) { g_red[0] = M; g_red[1] = logf(sSum); }
}

// K7: output = logits - max - log(sumexp)
__global__ void k_lsm_write(float* __restrict__ out) {
    int i = blockIdx.x * blockDim.x + threadIdx.x;
    if (i < V) out[OUT_OUTPUT + i] = g_logits[i] - g_red[0] - g_red[1];
}

extern "C" void kernel_launch(void* const* d_in, const int* in_sizes, int n_in,
                              void* d_out, int out_size) {
    const int*   word         = (const int*)d_in[0];
    const float* last_context = (const float*)d_in[1];
    const float* last_hidden  = (const float*)d_in[2];
    const float* enc          = (const float*)d_in[3];
    const float* embedding    = (const float*)d_in[4];
    const float* w_ih         = (const float*)d_in[5];
    const float* w_hh         = (const float*)d_in[6];
    const float* b_ih         = (const float*)d_in[7];
    const float* b_hh         = (const float*)d_in[8];
    const float* out_w        = (const float*)d_in[9];
    const float* out_b        = (const float*)d_in[10];
    float* out = (float*)d_out;

    k_gates    <<<768, 256>>>(word, embedding, last_context, w_ih, w_hh,
                              b_ih, b_hh, last_hidden);
    k_scores   <<<512, 256>>>(enc, last_hidden, out);
    k_softmax  <<<1, 1024>>>(out);
    k_ctx_part <<<NPART, 256>>>(enc);
    k_ctx_sum  <<<H / 256, 256>>>(out);
    k_logits   <<<(V + 7) / 8, 256>>>(out_w, out_b);
    k_lsm_red  <<<1, 1024>>>();
    k_lsm_write<<<(V + 255) / 256, 256>>>(out);
}

// round 5
// speedup vs baseline: 1.0589x; 1.0118x over previous
#include <cuda_runtime.h>
#include <math.h>

#define H   1024
#define H2  2048
#define H3  3072
#define SS  4096
#define V   50257

#define NPART 512            // ctx partial chunks (8 rows each)

// ---- scratch (no allocations allowed) ----
__device__ float g_gi[H3];
__device__ float g_gh[H3];
__device__ float g_scores[SS];
__device__ float g_attn[SS];
__device__ float g_y[H2];                  // [h_new, context]
__device__ float4 g_cpart[NPART][H / 4];   // context partials (deterministic)
__device__ float g_logits[V + 16];
__device__ float g_red[2];                 // max, log(sumexp)

// output layout (tuple order): output[V], context[H], h_new[H], attn[S]
#define OUT_OUTPUT  0
#define OUT_CONTEXT (V)
#define OUT_HNEW    (V + H)
#define OUT_ATTN    (V + 2 * H)

__device__ __forceinline__ float warpReduceSum(float v) {
    #pragma unroll
    for (int o = 16; o > 0; o >>= 1) v += __shfl_down_sync(0xffffffffu, v, o);
    return v;
}
__device__ __forceinline__ float warpReduceMax(float v) {
    #pragma unroll
    for (int o = 16; o > 0; o >>= 1) v = fmaxf(v, __shfl_down_sync(0xffffffffu, v, o));
    return v;
}
__device__ __forceinline__ float dot4(float4 a, float4 b) {
    return a.x * b.x + a.y * b.y + a.z * b.z + a.w * b.w;
}

// K1: gi = w_ih@[emb,ctx] + b_ih ; gh = w_hh@h + b_hh.
// Warp-per-row, 8 rows/block. Plain loads: w_ih/w_hh (37.7MB) should stay
// L2-resident across graph replays (only out_w is marked evict-first).
__global__ void __launch_bounds__(256) k_gates(
        const int* __restrict__ word,
        const float* __restrict__ emb,
        const float* __restrict__ ctx,
        const float* __restrict__ w_ih,
        const float* __restrict__ w_hh,
        const float* __restrict__ b_ih,
        const float* __restrict__ b_hh,
        const float* __restrict__ h) {
    __shared__ float4 sv[H2 / 4];
    int b = blockIdx.x;
    int tid = threadIdx.x;
    bool ih = (b < 384);
    if (ih) {
        const float4* e4 = (const float4*)(emb + (size_t)word[0] * H);
        sv[tid] = e4[tid];
        sv[256 + tid] = ((const float4*)ctx)[tid];
    } else {
        sv[tid] = ((const float4*)h)[tid];
    }
    __syncthreads();

    int warp = tid >> 5, lane = tid & 31;
    if (ih) {
        int row = b * 8 + warp;
        const float4* w4 = (const float4*)(w_ih + (size_t)row * H2);
        float acc = 0.f;
        #pragma unroll
        for (int i = 0; i < 16; i++) {
            int j = lane + 32 * i;
            acc += dot4(w4[j], sv[j]);
        }
        acc = warpReduceSum(acc);
        if (lane == 0) g_gi[row] = acc + b_ih[row];
    } else {
        int row = (b - 384) * 8 + warp;
        const float4* w4 = (const float4*)(w_hh + (size_t)row * H);
        float acc = 0.f;
        #pragma unroll
        for (int i = 0; i < 8; i++) {
            int j = lane + 32 * i;
            acc += dot4(w4[j], sv[j]);
        }
        acc = warpReduceSum(acc);
        if (lane == 0) g_gh[row] = acc + b_hh[row];
    }
}

// K2: fused GRU pointwise (recomputed per block into smem) + attention scores.
// Warp-per-row, 8 rows/block, 512 blocks. Block 0 also publishes h_new.
__global__ void __launch_bounds__(256) k_scores(
        const float* __restrict__ enc,
        const float* __restrict__ h,
        float* __restrict__ out) {
    __shared__ float4 sh[H / 4];
    int tid = threadIdx.x;
    for (int i = tid; i < H; i += 256) {
        float r = 1.f / (1.f + expf(-(g_gi[i]     + g_gh[i])));
        float z = 1.f / (1.f + expf(-(g_gi[H + i] + g_gh[H + i])));
        float n = tanhf(g_gi[2 * H + i] + r * g_gh[2 * H + i]);
        float hn = (1.f - z) * n + z * h[i];
        ((float*)sh)[i] = hn;
        if (blockIdx.x == 0) {
            g_y[i] = hn;
            out[OUT_HNEW + i] = hn;
        }
    }
    __syncthreads();

    int warp = tid >> 5, lane = tid & 31;
    int row = blockIdx.x * 8 + warp;
    const float4* e4 = (const float4*)(enc + (size_t)row * H);
    float acc = 0.f;
    #pragma unroll
    for (int i = 0; i < 8; i++) {
        int j = lane + 32 * i;
        acc += dot4(e4[j], sh[j]);
    }
    acc = warpReduceSum(acc);
    if (lane == 0) g_scores[row] = acc;
}

// K3: softmax over S=4096 (single block). Writes attn output slot.
__global__ void k_softmax(float* __restrict__ out) {
    __shared__ float sred[32];
    __shared__ float sM, sSum;
    int tid = threadIdx.x;
    int wid = tid >> 5, lane = tid & 31;

    float m = -1e30f;
    for (int i = tid; i < SS; i += 1024) m = fmaxf(m, g_scores[i]);
    m = warpReduceMax(m);
    if (lane == 0) sred[wid] = m;
    __syncthreads();
    if (wid == 0) {
        m = sred[lane];
        m = warpReduceMax(m);
        if (lane == 0) sM = m;
    }
    __syncthreads();
    float M = sM;

    float s = 0.f;
    for (int i = tid; i < SS; i += 1024) s += expf(g_scores[i] - M);
    s = warpReduceSum(s);
    if (lane == 0) sred[wid] = s;
    __syncthreads();
    if (wid == 0) {
        s = sred[lane];
        s = warpReduceSum(s);
        if (lane == 0) sSum = s;
    }
    __syncthreads();
    float inv = 1.f / sSum;

    for (int i = tid; i < SS; i += 1024) {
        float a = expf(g_scores[i] - M) * inv;
        g_attn[i] = a;
        out[OUT_ATTN + i] = a;
    }
}

// K4: logits (h half) = out_w[:, 0:H] @ h_new + out_b.
// Warp per row, 8 rows/block, streaming (evict-first) loads on out_w.
// Launch position 4 -> this is the kernel ncu captures.
__global__ void __launch_bounds__(256) k_logits_h(const float* __restrict__ out_w,
                                                  const float* __restrict__ out_b) {
    __shared__ float4 sy[H / 4];
    for (int j = threadIdx.x; j < H / 4; j += blockDim.x)
        sy[j] = ((const float4*)g_y)[j];
    __syncthreads();

    int warp = threadIdx.x >> 5, lane = threadIdx.x & 31;
    int row = blockIdx.x * 8 + warp;
    if (row >= V) return;

    const float4* w4 = (const float4*)(out_w + (size_t)row * H2);
    float acc = 0.f;
    #pragma unroll
    for (int i = 0; i < 8; i++) {
        int j = lane + 32 * i;
        acc += dot4(__ldcs(w4 + j), sy[j]);
    }
    acc = warpReduceSum(acc);
    if (lane == 0) g_logits[row] = acc + out_b[row];
}

// K5: context partials. 512 blocks (s-chunks of 8 rows), 256 threads,
// each thread one float4 column.
__global__ void __launch_bounds__(256) k_ctx_part(const float* __restrict__ enc) {
    int c4 = threadIdx.x;
    int s0 = blockIdx.x * 8;
    const float4* e4 = (const float4*)enc;
    float4 acc = make_float4(0.f, 0.f, 0.f, 0.f);
    #pragma unroll
    for (int k = 0; k < 8; k++) {
        float a = g_attn[s0 + k];
        float4 e = e4[(size_t)(s0 + k) * (H / 4) + c4];
        acc.x += a * e.x; acc.y += a * e.y; acc.z += a * e.z; acc.w += a * e.w;
    }
    g_cpart[blockIdx.x][c4] = acc;
}

// K6: sum NPART partials per column (deterministic). Writes context + y[H:2H].
__global__ void __launch_bounds__(256) k_ctx_sum(float* __restrict__ out) {
    int col = blockIdx.x * 256 + threadIdx.x;
    const float* cp = (const float*)g_cpart;
    float a0 = 0.f, a1 = 0.f, a2 = 0.f, a3 = 0.f;
    #pragma unroll 8
    for (int p = 0; p < NPART; p += 4) {
        a0 += cp[(p    ) * H + col];
        a1 += cp[(p + 1) * H + col];
        a2 += cp[(p + 2) * H + col];
        a3 += cp[(p + 3) * H + col];
    }
    float acc = (a0 + a1) + (a2 + a3);
    out[OUT_CONTEXT + col] = acc;
    g_y[H + col] = acc;
}

// K7: logits += out_w[:, H:2H] @ context.
__global__ void __launch_bounds__(256) k_logits_c(const float* __restrict__ out_w) {
    __shared__ float4 sy[H / 4];
    for (int j = threadIdx.x; j < H / 4; j += blockDim.x)
        sy[j] = ((const float4*)(g_y + H))[j];
    __syncthreads();

    int warp = threadIdx.x >> 5, lane = threadIdx.x & 31;
    int row = blockIdx.x * 8 + warp;
    if (row >= V) return;

    const float4* w4 = (const float4*)(out_w + (size_t)row * H2 + H);
    float acc = 0.f;
    #pragma unroll
    for (int i = 0; i < 8; i++) {
        int j = lane + 32 * i;
        acc += dot4(__ldcs(w4 + j), sy[j]);
    }
    acc = warpReduceSum(acc);
    if (lane == 0) g_logits[row] += acc;
}

// K8: log-softmax reduction (single block, 1024 threads).
__global__ void k_lsm_red() {
    __shared__ float sred[32];
    __shared__ float sM, sSum;
    int tid = threadIdx.x;
    int wid = tid >> 5, lane = tid & 31;

    float m = -1e30f;
    for (int i = tid; i < V; i += 1024) m = fmaxf(m, g_logits[i]);
    m = warpReduceMax(m);
    if (lane == 0) sred[wid] = m;
    __syncthreads();
    if (wid == 0) {
        m = sred[lane];
        m = warpReduceMax(m);
        if (lane == 0) sM = m;
    }
    __syncthreads();
    float M = sM;

    float s = 0.f;
    for (int i = tid; i < V; i += 1024) s += expf(g_logits[i] - M);
    s = warpReduceSum(s);
    if (lane == 0) sred[wid] = s;
    __syncthreads();
    if (wid == 0) {
        s = sred[lane];
        s = warpReduceSum(s);
        if (lane == 0) sSum = s;
    }
    __syncthreads();
    if (tid == 0) { g_red[0] = M; g_red[1] = logf(sSum); }
}

// K9: output = logits - max - log(sumexp)
__global__ void k_lsm_write(float* __restrict__ out) {
    int i = blockIdx.x * blockDim.x + threadIdx.x;
    if (i < V) out[OUT_OUTPUT + i] = g_logits[i] - g_red[0] - g_red[1];
}

extern "C" void kernel_launch(void* const* d_in, const int* in_sizes, int n_in,
                              void* d_out, int out_size) {
    const int*   word         = (const int*)d_in[0];
    const float* last_context = (const float*)d_in[1];
    const float* last_hidden  = (const float*)d_in[2];
    const float* enc          = (const float*)d_in[3];
    const float* embedding    = (const float*)d_in[4];
    const float* w_ih         = (const float*)d_in[5];
    const float* w_hh         = (const float*)d_in[6];
    const float* b_ih         = (const float*)d_in[7];
    const float* b_hh         = (const float*)d_in[8];
    const float* out_w        = (const float*)d_in[9];
    const float* out_b        = (const float*)d_in[10];
    float* out = (float*)d_out;

    k_gates    <<<768, 256>>>(word, embedding, last_context, w_ih, w_hh,
                              b_ih, b_hh, last_hidden);
    k_scores   <<<512, 256>>>(enc, last_hidden, out);
    k_softmax  <<<1, 1024>>>(out);
    k_logits_h <<<(V + 7) / 8, 256>>>(out_w, out_b);   // position 4 -> profiled
    k_ctx_part <<<NPART, 256>>>(enc);
    k_ctx_sum  <<<H / 256, 256>>>(out);
    k_logits_c <<<(V + 7) / 8, 256>>>(out_w);
    k_lsm_red  <<<1, 1024>>>();
    k_lsm_write<<<(V + 255) / 256, 256>>>(out);
}